// round 3
// baseline (speedup 1.0000x reference)
#include <cuda_runtime.h>

// RelationAwareAttention: B=1, H=8, L=512, D=64
// out = concat(attn_sum[1,8,512,64], p_attn[1,8,512,512]) as float32.

#define L_SEQ 512
#define D_DIM 64
#define H_HEADS 8
#define NTHREADS 256

__global__ __launch_bounds__(NTHREADS)
void rel_attn_kernel(const float* __restrict__ q_g,
                     const float* __restrict__ k_g,
                     const float* __restrict__ v_g,
                     const float* __restrict__ rk_g,
                     const float* __restrict__ rv_g,
                     const int*   __restrict__ mask_g,
                     float* __restrict__ out_attn,
                     float* __restrict__ out_p)
{
    const int i    = blockIdx.x;   // query position
    const int h    = blockIdx.y;   // head
    const int tid  = threadIdx.x;
    const int warp = tid >> 5;
    const int lane = tid & 31;

    __shared__ float  s_score[L_SEQ];
    __shared__ float  s_red[8];
    __shared__ float2 s_acc[8][32];

    const float* q    = q_g  + ((size_t)h * L_SEQ + i) * D_DIM;
    const float* krow = k_g  + (size_t)h * L_SEQ * D_DIM;
    const float* rk   = rk_g + (((size_t)h * L_SEQ + i) * L_SEQ) * D_DIM;
    const int*   mrow = mask_g + (size_t)i * L_SEQ;   // mask broadcast over h (B=1)

    // ---------------- Phase 1: scores ----------------
    // score[j] = (q . (k[j] + rk[i,j])) / sqrt(64), masked.
    // Warp w owns j in [w*64, (w+1)*64). Lane loads float2 at d = 2*lane.
    const float2 q2 = *reinterpret_cast<const float2*>(q + 2 * lane);

    #pragma unroll 4
    for (int jj = 0; jj < 64; ++jj) {
        const int j = (warp << 6) + jj;
        const float2 kv = *reinterpret_cast<const float2*>(krow + (size_t)j * D_DIM + 2 * lane);
        const float2 rv = *reinterpret_cast<const float2*>(rk   + (size_t)j * D_DIM + 2 * lane);
        float p = q2.x * (kv.x + rv.x) + q2.y * (kv.y + rv.y);
        p += __shfl_xor_sync(0xffffffffu, p, 16);
        p += __shfl_xor_sync(0xffffffffu, p, 8);
        p += __shfl_xor_sync(0xffffffffu, p, 4);
        p += __shfl_xor_sync(0xffffffffu, p, 2);
        p += __shfl_xor_sync(0xffffffffu, p, 1);
        if (lane == 0) {
            float s = p * 0.125f;                 // 1/sqrt(64)
            if (mrow[j] == 0) s = -1e9f;
            s_score[j] = s;
        }
    }
    __syncthreads();

    // ---------------- Phase 2: softmax over j ----------------
    // Each thread owns scores tid and tid+256.
    float v0 = s_score[tid];
    float v1 = s_score[tid + 256];

    // max-reduce
    float m = fmaxf(v0, v1);
    #pragma unroll
    for (int o = 16; o > 0; o >>= 1)
        m = fmaxf(m, __shfl_xor_sync(0xffffffffu, m, o));
    if (lane == 0) s_red[warp] = m;
    __syncthreads();
    if (tid == 0) {
        float mm = s_red[0];
        #pragma unroll
        for (int w = 1; w < 8; ++w) mm = fmaxf(mm, s_red[w]);
        s_red[0] = mm;
    }
    __syncthreads();
    m = s_red[0];
    __syncthreads();   // protect s_red before reuse

    // exp + sum-reduce
    const float e0 = __expf(v0 - m);
    const float e1 = __expf(v1 - m);
    float ssum = e0 + e1;
    #pragma unroll
    for (int o = 16; o > 0; o >>= 1)
        ssum += __shfl_xor_sync(0xffffffffu, ssum, o);
    if (lane == 0) s_red[warp] = ssum;
    __syncthreads();
    if (tid == 0) {
        float tot = s_red[0];
        #pragma unroll
        for (int w = 1; w < 8; ++w) tot += s_red[w];
        s_red[0] = tot;
    }
    __syncthreads();
    const float inv = 1.0f / s_red[0];

    const float p0 = e0 * inv;
    const float p1 = e1 * inv;
    s_score[tid]       = p0;
    s_score[tid + 256] = p1;

    // write p_attn (coalesced)
    const size_t pbase = ((size_t)h * L_SEQ + i) * L_SEQ;
    out_p[pbase + tid]       = p0;
    out_p[pbase + tid + 256] = p1;
    __syncthreads();

    // ---------------- Phase 3: output = sum_j p[j] * (v[j] + rv[i,j]) ----------------
    // Thread layout: 32 d-pairs x 8 j-groups. Lane = d-pair (float2), warp = j-group.
    const int dp = lane;          // float2 index: d = 2*dp
    const int g  = warp;          // j stride group
    const float* vrow = v_g  + (size_t)h * L_SEQ * D_DIM;
    const float* rv   = rv_g + (((size_t)h * L_SEQ + i) * L_SEQ) * D_DIM;

    float2 acc = make_float2(0.f, 0.f);
    #pragma unroll 4
    for (int j = g; j < L_SEQ; j += 8) {
        const float  pj = s_score[j];
        const float2 vv = *reinterpret_cast<const float2*>(vrow + (size_t)j * D_DIM + 2 * dp);
        const float2 rr = *reinterpret_cast<const float2*>(rv   + (size_t)j * D_DIM + 2 * dp);
        acc.x += pj * (vv.x + rr.x);
        acc.y += pj * (vv.y + rr.y);
    }
    s_acc[g][dp] = acc;
    __syncthreads();

    if (warp == 0) {
        float2 r = make_float2(0.f, 0.f);
        #pragma unroll
        for (int gg = 0; gg < 8; ++gg) {
            r.x += s_acc[gg][dp].x;
            r.y += s_acc[gg][dp].y;
        }
        float2* oa = reinterpret_cast<float2*>(out_attn + ((size_t)h * L_SEQ + i) * D_DIM);
        oa[dp] = r;
    }
}

extern "C" void kernel_launch(void* const* d_in, const int* in_sizes, int n_in,
                              void* d_out, int out_size)
{
    const float* q    = (const float*)d_in[0];
    const float* k    = (const float*)d_in[1];
    const float* v    = (const float*)d_in[2];
    const float* rk   = (const float*)d_in[3];
    const float* rv   = (const float*)d_in[4];
    const int*   mask = (const int*)  d_in[5];

    float* out      = (float*)d_out;
    float* out_attn = out;                                        // [1,8,512,64]
    float* out_p    = out + (size_t)H_HEADS * L_SEQ * D_DIM;      // [1,8,512,512]

    dim3 grid(L_SEQ, H_HEADS);
    rel_attn_kernel<<<grid, NTHREADS>>>(q, k, v, rk, rv, mask, out_attn, out_p);
}

// round 5
// speedup vs baseline: 1.3181x; 1.3181x over previous
#include <cuda_runtime.h>

// RelationAwareAttention: B=1, H=8, L=512, D=64
// out = concat(attn_sum[1,8,512,64], p_attn[1,8,512,512]) as float32.

#define L_SEQ 512
#define D_DIM 64
#define H_HEADS 8
#define NTHREADS 256

__global__ __launch_bounds__(NTHREADS)
void rel_attn_kernel(const float* __restrict__ q_g,
                     const float* __restrict__ k_g,
                     const float* __restrict__ v_g,
                     const float* __restrict__ rk_g,
                     const float* __restrict__ rv_g,
                     const int*   __restrict__ mask_g,
                     float* __restrict__ out_attn,
                     float* __restrict__ out_p)
{
    const int i    = blockIdx.x;   // query position
    const int h    = blockIdx.y;   // head
    const int tid  = threadIdx.x;
    const int warp = tid >> 5;
    const int lane = tid & 31;
    const int half = lane >> 4;    // 0 or 1: which j this half-warp owns
    const int hl   = lane & 15;    // lane within half-warp

    __shared__ float  s_score[L_SEQ];
    __shared__ float  s_red[8];
    __shared__ float4 s_acc[16][16];   // [j-group][d-quad]

    const float* q    = q_g  + ((size_t)h * L_SEQ + i) * D_DIM;
    const float* krow = k_g  + (size_t)h * L_SEQ * D_DIM;
    const float* rk   = rk_g + (((size_t)h * L_SEQ + i) * L_SEQ) * D_DIM;
    const int*   mrow = mask_g + (size_t)i * L_SEQ;   // mask broadcast over h (B=1)

    // ---------------- Phase 1: scores ----------------
    // score[j] = (q . (k[j] + rk[i,j])) / sqrt(64), masked.
    // Warp w owns j in [w*64, (w+1)*64). Each half-warp (16 lanes x float4)
    // computes one j per iteration -> 2 j's per warp per iteration.
    const float4 q4 = *reinterpret_cast<const float4*>(q + 4 * hl);

    #pragma unroll 4
    for (int jj = 0; jj < 32; ++jj) {
        const int j = (warp << 6) + (jj << 1) + half;
        const float4 kv = *reinterpret_cast<const float4*>(krow + (size_t)j * D_DIM + 4 * hl);
        const float4 rr = *reinterpret_cast<const float4*>(rk   + (size_t)j * D_DIM + 4 * hl);
        float p = q4.x * (kv.x + rr.x) + q4.y * (kv.y + rr.y)
                + q4.z * (kv.z + rr.z) + q4.w * (kv.w + rr.w);
        // reduce over the 16 lanes of this half-warp (xor masks stay within half)
        p += __shfl_xor_sync(0xffffffffu, p, 8);
        p += __shfl_xor_sync(0xffffffffu, p, 4);
        p += __shfl_xor_sync(0xffffffffu, p, 2);
        p += __shfl_xor_sync(0xffffffffu, p, 1);
        if (hl == 0) {
            float s = p * 0.125f;                 // 1/sqrt(64)
            if (mrow[j] == 0) s = -1e9f;
            s_score[j] = s;
        }
    }
    __syncthreads();

    // ---------------- Phase 2: softmax over j ----------------
    // Each thread owns scores tid and tid+256.
    float v0 = s_score[tid];
    float v1 = s_score[tid + 256];

    // max-reduce
    float m = fmaxf(v0, v1);
    #pragma unroll
    for (int o = 16; o > 0; o >>= 1)
        m = fmaxf(m, __shfl_xor_sync(0xffffffffu, m, o));
    if (lane == 0) s_red[warp] = m;
    __syncthreads();
    if (tid == 0) {
        float mm = s_red[0];
        #pragma unroll
        for (int w = 1; w < 8; ++w) mm = fmaxf(mm, s_red[w]);
        s_red[0] = mm;
    }
    __syncthreads();
    m = s_red[0];
    __syncthreads();   // protect s_red before reuse

    // exp + sum-reduce
    const float e0 = __expf(v0 - m);
    const float e1 = __expf(v1 - m);
    float ssum = e0 + e1;
    #pragma unroll
    for (int o = 16; o > 0; o >>= 1)
        ssum += __shfl_xor_sync(0xffffffffu, ssum, o);
    if (lane == 0) s_red[warp] = ssum;
    __syncthreads();
    if (tid == 0) {
        float tot = s_red[0];
        #pragma unroll
        for (int w = 1; w < 8; ++w) tot += s_red[w];
        s_red[0] = tot;
    }
    __syncthreads();
    const float inv = 1.0f / s_red[0];

    const float p0 = e0 * inv;
    const float p1 = e1 * inv;
    s_score[tid]       = p0;
    s_score[tid + 256] = p1;

    // write p_attn (coalesced)
    const size_t pbase = ((size_t)h * L_SEQ + i) * L_SEQ;
    out_p[pbase + tid]       = p0;
    out_p[pbase + tid + 256] = p1;
    __syncthreads();

    // ---------------- Phase 3: output = sum_j p[j] * (v[j] + rv[i,j]) ----------------
    // 16 j-groups (warp*2 + half), each 16 lanes x float4 over d.
    const int gid = (warp << 1) + half;
    const float* vrow = v_g  + (size_t)h * L_SEQ * D_DIM;
    const float* rv   = rv_g + (((size_t)h * L_SEQ + i) * L_SEQ) * D_DIM;

    float4 acc = make_float4(0.f, 0.f, 0.f, 0.f);
    #pragma unroll 4
    for (int j = gid; j < L_SEQ; j += 16) {
        const float  pj = s_score[j];
        const float4 vv = *reinterpret_cast<const float4*>(vrow + (size_t)j * D_DIM + 4 * hl);
        const float4 rr = *reinterpret_cast<const float4*>(rv   + (size_t)j * D_DIM + 4 * hl);
        acc.x += pj * (vv.x + rr.x);
        acc.y += pj * (vv.y + rr.y);
        acc.z += pj * (vv.z + rr.z);
        acc.w += pj * (vv.w + rr.w);
    }
    s_acc[gid][hl] = acc;
    __syncthreads();

    if (tid < 16) {
        float4 r = make_float4(0.f, 0.f, 0.f, 0.f);
        #pragma unroll
        for (int gg = 0; gg < 16; ++gg) {
            const float4 a = s_acc[gg][tid];
            r.x += a.x; r.y += a.y; r.z += a.z; r.w += a.w;
        }
        float4* oa = reinterpret_cast<float4*>(out_attn + ((size_t)h * L_SEQ + i) * D_DIM);
        oa[tid] = r;
    }
}

extern "C" void kernel_launch(void* const* d_in, const int* in_sizes, int n_in,
                              void* d_out, int out_size)
{
    const float* q    = (const float*)d_in[0];
    const float* k    = (const float*)d_in[1];
    const float* v    = (const float*)d_in[2];
    const float* rk   = (const float*)d_in[3];
    const float* rv   = (const float*)d_in[4];
    const int*   mask = (const int*)  d_in[5];

    float* out      = (float*)d_out;
    float* out_attn = out;                                        // [1,8,512,64]
    float* out_p    = out + (size_t)H_HEADS * L_SEQ * D_DIM;      // [1,8,512,512]

    dim3 grid(L_SEQ, H_HEADS);
    rel_attn_kernel<<<grid, NTHREADS>>>(q, k, v, rk, rv, mask, out_attn, out_p);
}